// round 7
// baseline (speedup 1.0000x reference)
#include <cuda_runtime.h>
#include <cstddef>

// ---------------------------------------------------------------------------
// RBFolution: out[b,oh,ow,f] = exp(-beta[f] * (||p||^2 - 2 p.ccs[:,f] + ||ccs[:,f]||^2))
// with p = 3x3xC valid patch of x at (oh,ow).  B=32,H=W=112,C=32,F=128,D=288.
//
// Implicit-GEMM SIMT kernel, full FP32 (precision requirement: score ~400,
// out rel-err ~= beta * score-err, so TF32-class K-products are not allowed).
//
// Block: 256 threads, tile 16x8 pixels x 128 filters.
//   fid = tid & 15  -> filters [fid*4 .. fid*4+3] and [64+fid*4 .. 64+fid*4+3]
//   pid = tid >> 4  -> pixel row within tile; 8 pixel columns per thread
// Full ccs (147 KB) + halo x tile (23 KB, row pitch padded for bank-conflict-
// free A broadcast) resident in shared memory. occ = 1 block/SM, 8 warps.
// ---------------------------------------------------------------------------

#define Bn 32
#define Hn 112
#define Wn 112
#define Cn 32
#define Fn 128
#define HoN 110
#define WoN 110
#define Dn 288            // 3*3*Cn

#define TILE_H 16
#define TILE_W 8
#define THREADS 256

#define XS_H (TILE_H + 2)         // 18
#define XS_W (TILE_W + 2)         // 10
#define XS_RPITCH (XS_W * Cn + 4) // 324 floats: +4 pad -> pid-pair hits different banks

#define SMEM_FLOATS (Dn * Fn + XS_H * XS_RPITCH + TILE_H * TILE_W + Fn + Fn)
#define SMEM_BYTES (SMEM_FLOATS * 4)

__global__ void __launch_bounds__(THREADS, 1)
rbfolution_kernel(const float* __restrict__ x,
                  const float* __restrict__ ccs,
                  const float* __restrict__ beta,
                  float* __restrict__ out)
{
    extern __shared__ float smem[];
    float* sccs  = smem;                         // [Dn][Fn]      147456 B
    float* xs    = sccs + Dn * Fn;               // [XS_H][XS_RPITCH]
    float* psq   = xs + XS_H * XS_RPITCH;        // [128] per-pixel ||p||^2
    float* csq   = psq + TILE_H * TILE_W;        // [128] per-filter ||c||^2
    float* sbeta = csq + Fn;                     // [128]

    const int tid = threadIdx.x;
    const int b   = blockIdx.z;
    const int oh0 = blockIdx.y * TILE_H;
    const int ow0 = blockIdx.x * TILE_W;

    // ---- load full ccs into smem (contiguous float4 copy) ----
    {
        const float4* src = reinterpret_cast<const float4*>(ccs);
        float4* dst = reinterpret_cast<float4*>(sccs);
        #pragma unroll
        for (int i = 0; i < (Dn * Fn / 4) / THREADS; ++i)
            dst[tid + i * THREADS] = src[tid + i * THREADS];
    }

    // ---- load x halo tile (18 x 10 x 32), zero-fill out-of-bounds ----
    {
        const int NV = XS_H * XS_W * (Cn / 4);   // 1440 float4 slots (logical)
        for (int i = tid; i < NV; i += THREADS) {
            int pos = i / (Cn / 4);
            int v   = i % (Cn / 4);
            int r   = pos / XS_W;
            int col = pos % XS_W;
            int gr  = oh0 + r;
            int gc  = ow0 + col;
            float4 val = make_float4(0.f, 0.f, 0.f, 0.f);
            if (gr < Hn && gc < Wn) {
                val = *reinterpret_cast<const float4*>(
                    x + (((size_t)b * Hn + gr) * Wn + gc) * Cn + v * 4);
            }
            // xs row pitch is padded; write as 4 scalars at padded address
            float* d = xs + r * XS_RPITCH + col * Cn + v * 4;
            d[0] = val.x; d[1] = val.y; d[2] = val.z; d[3] = val.w;
        }
    }
    __syncthreads();

    // ---- warps 0-3: per-pixel ||p||^2 ; warps 4-7: per-filter ||c||^2 + beta ----
    if (tid < TILE_H * TILE_W) {
        const int ty = tid >> 3;   // 0..15
        const int tx = tid & 7;    // 0..7
        float s = 0.f;
        #pragma unroll
        for (int tr = 0; tr < 3; ++tr) {
            #pragma unroll
            for (int tc = 0; tc < 3; ++tc) {
                const float* p = xs + (ty + tr) * XS_RPITCH + (tx + tc) * Cn;
                #pragma unroll
                for (int c = 0; c < Cn; ++c) {
                    float v = p[c];
                    s = fmaf(v, v, s);
                }
            }
        }
        psq[tid] = s;
    } else {
        const int f = tid - 128;
        float s = 0.f;
        #pragma unroll 8
        for (int d = 0; d < Dn; ++d) {
            float v = sccs[d * Fn + f];
            s = fmaf(v, v, s);
        }
        csq[f] = s;
        sbeta[f] = beta[f];
    }
    __syncthreads();

    // ---- main loop: acc[px][j] = dot(p, ccs[:, f]) ----
    const int fid = tid & 15;     // filter group
    const int pid = tid >> 4;     // pixel row within tile

    float acc[8][8];
    #pragma unroll
    for (int i = 0; i < 8; ++i)
        #pragma unroll
        for (int j = 0; j < 8; ++j)
            acc[i][j] = 0.f;

    #pragma unroll 1
    for (int tr = 0; tr < 3; ++tr) {
        #pragma unroll 1
        for (int tc = 0; tc < 3; ++tc) {
            const float* ap = xs + (pid + tr) * XS_RPITCH + tc * Cn;
            const float* bp = sccs + (size_t)(tr * 3 + tc) * Cn * Fn + fid * 4;
            #pragma unroll 8
            for (int c = 0; c < Cn; ++c) {
                const float4 b0 = *reinterpret_cast<const float4*>(bp + c * Fn);
                const float4 b1 = *reinterpret_cast<const float4*>(bp + c * Fn + 64);
                #pragma unroll
                for (int px = 0; px < 8; ++px) {
                    const float a = ap[px * Cn + c];
                    acc[px][0] = fmaf(a, b0.x, acc[px][0]);
                    acc[px][1] = fmaf(a, b0.y, acc[px][1]);
                    acc[px][2] = fmaf(a, b0.z, acc[px][2]);
                    acc[px][3] = fmaf(a, b0.w, acc[px][3]);
                    acc[px][4] = fmaf(a, b1.x, acc[px][4]);
                    acc[px][5] = fmaf(a, b1.y, acc[px][5]);
                    acc[px][6] = fmaf(a, b1.z, acc[px][6]);
                    acc[px][7] = fmaf(a, b1.w, acc[px][7]);
                }
            }
        }
    }

    // ---- epilogue: score = psq + csq - 2*dot ; out = exp(-beta*score) ----
    const int oh = oh0 + pid;
    if (oh < HoN) {
        const int f0 = fid * 4;
        const float cs0 = csq[f0 + 0], cs1 = csq[f0 + 1];
        const float cs2 = csq[f0 + 2], cs3 = csq[f0 + 3];
        const float cs4 = csq[f0 + 64], cs5 = csq[f0 + 65];
        const float cs6 = csq[f0 + 66], cs7 = csq[f0 + 67];
        const float bt0 = sbeta[f0 + 0], bt1 = sbeta[f0 + 1];
        const float bt2 = sbeta[f0 + 2], bt3 = sbeta[f0 + 3];
        const float bt4 = sbeta[f0 + 64], bt5 = sbeta[f0 + 65];
        const float bt6 = sbeta[f0 + 66], bt7 = sbeta[f0 + 67];

        #pragma unroll
        for (int px = 0; px < 8; ++px) {
            const int ow = ow0 + px;
            if (ow < WoN) {
                const float ps = psq[pid * TILE_W + px];
                float4 r0, r1;
                r0.x = __expf(-bt0 * (ps + cs0 - 2.f * acc[px][0]));
                r0.y = __expf(-bt1 * (ps + cs1 - 2.f * acc[px][1]));
                r0.z = __expf(-bt2 * (ps + cs2 - 2.f * acc[px][2]));
                r0.w = __expf(-bt3 * (ps + cs3 - 2.f * acc[px][3]));
                r1.x = __expf(-bt4 * (ps + cs4 - 2.f * acc[px][4]));
                r1.y = __expf(-bt5 * (ps + cs5 - 2.f * acc[px][5]));
                r1.z = __expf(-bt6 * (ps + cs6 - 2.f * acc[px][6]));
                r1.w = __expf(-bt7 * (ps + cs7 - 2.f * acc[px][7]));
                float* op = out + (((size_t)b * HoN + oh) * WoN + ow) * Fn + f0;
                *reinterpret_cast<float4*>(op)      = r0;
                *reinterpret_cast<float4*>(op + 64) = r1;
            }
        }
    }
}

extern "C" void kernel_launch(void* const* d_in, const int* in_sizes, int n_in,
                              void* d_out, int out_size)
{
    (void)in_sizes; (void)n_in; (void)out_size;
    const float* x    = (const float*)d_in[0];
    const float* ccs  = (const float*)d_in[1];
    const float* beta = (const float*)d_in[2];
    float* out = (float*)d_out;

    // Opt-in to >48KB dynamic smem (idempotent, not a stream op -> capture-safe).
    cudaFuncSetAttribute(rbfolution_kernel,
                         cudaFuncAttributeMaxDynamicSharedMemorySize, SMEM_BYTES);

    dim3 grid((WoN + TILE_W - 1) / TILE_W,   // 14
              (HoN + TILE_H - 1) / TILE_H,   // 7
              Bn);                           // 32
    rbfolution_kernel<<<grid, THREADS, SMEM_BYTES>>>(x, ccs, beta, out);
}